// round 8
// baseline (speedup 1.0000x reference)
#include <cuda_runtime.h>

#define T_STEPS 1024
#define BATCH   2048
#define N1      30
#define N2      60

using ull = unsigned long long;

// packed fp32x2 FMA
__device__ __forceinline__ ull ffma2(ull a, ull b, ull c) {
    ull d;
    asm("fma.rn.f32x2 %0, %1, %2, %3;" : "=l"(d) : "l"(a), "l"(b), "l"(c));
    return d;
}
__device__ __forceinline__ ull pk2(float x, float y) {
    ull r;
    asm("mov.b64 %0, {%1, %2};" : "=l"(r) : "f"(x), "f"(y));
    return r;
}
__device__ __forceinline__ float hadd2(ull v) {
    float a, b;
    asm("mov.b64 {%0, %1}, %2;" : "=f"(a), "=f"(b) : "l"(v));
    return a + b;
}
__device__ __forceinline__ float ftanh(float x) {
    float e = __expf(-2.f * x);
    return __fdividef(1.f - e, 1.f + e);
}

// Block = 64 threads = 2 warps, owning batch pair (b0, b0+1). ALL weights in regs:
//   r2: warp w lane l<30 owns row2 = w*30+l   -> W22 row (30 ull) + W21m row (15 ull)
//   r1: warp w lanes 2i,2i+1 (i<15) own the two 16-wide halves (padded) of r1 row 15w+i
//       -> W11 half (8 ull); combine via shfl_xor(1)
__global__ void __launch_bounds__(64, 7) hier_rnn_kernel(
    const float* __restrict__ inp,    // (T, B, 1)
    const float* __restrict__ noise1, // (T, B, N1)
    const float* __restrict__ noise2, // (T, B, N2)
    const float* __restrict__ W11,    // (N1, N1)
    const float* __restrict__ W22,    // (N2, N2)
    const float* __restrict__ W21,    // (N2, N1)
    const float* __restrict__ M21,    // (N2, N1)
    const float* __restrict__ Win,    // (N1,)
    const float* __restrict__ Wout,   // (N2,)
    float* __restrict__ out)          // (T, B, 1)
{
    __shared__ __align__(16) float s1buf[2][2][32];  // [buf][elem][slot], pads 30,31 = 0
    __shared__ __align__(16) float s2buf[2][2][64];  // [buf][elem][row], 60 used
    __shared__ float2 ypart[2];

    const int tid = threadIdx.x;
    const int w   = tid >> 5;
    const int l   = tid & 31;
    const int b0  = blockIdx.x * 2;

    const bool act2 = (l < 30);                  // owns an r2 row
    const int  row2 = w * 30 + (act2 ? l : 29);  // clamped
    const int  half = l & 1;
    const int  row1 = 15 * w + (act2 ? (l >> 1) : 0);  // clamped (lanes 30,31 -> i=0)

    // ---- weights in registers ----
    ull w22[30];                                  // 60 regs
    #pragma unroll
    for (int k = 0; k < 30; k++) {
        float2 v = act2 ? *(const float2*)(W22 + row2 * N2 + 2 * k) : make_float2(0.f, 0.f);
        w22[k] = pk2(v.x, v.y);
    }
    ull w21[15];                                  // 30 regs (mask folded in)
    #pragma unroll
    for (int k = 0; k < 15; k++) {
        float2 v = act2 ? *(const float2*)(W21 + row2 * N1 + 2 * k) : make_float2(0.f, 0.f);
        float2 m = act2 ? *(const float2*)(M21 + row2 * N1 + 2 * k) : make_float2(0.f, 0.f);
        w21[k] = pk2(v.x * m.x, v.y * m.y);
    }
    ull w11h[8];                                  // 16 regs: cols [16*half .. 16*half+15]
    #pragma unroll
    for (int k = 0; k < 8; k++) {
        int c0 = 16 * half + 2 * k;
        float vx = (act2 && c0     < N1) ? W11[row1 * N1 + c0]     : 0.f;
        float vy = (act2 && c0 + 1 < N1) ? W11[row1 * N1 + c0 + 1] : 0.f;
        w11h[k] = pk2(vx, vy);
    }
    const float winl  = act2 ? Win[row1]  : 0.f;
    const float woutl = act2 ? Wout[row2] : 0.f;

    // ---- zero state (both buffers; pads stay zero forever) ----
    ((float*)s1buf)[tid]       = 0.f;  ((float*)s1buf)[tid + 64]  = 0.f;
    ((float*)s2buf)[tid]       = 0.f;  ((float*)s2buf)[tid + 64]  = 0.f;
    ((float*)s2buf)[tid + 128] = 0.f;  ((float*)s2buf)[tid + 192] = 0.f;
    __syncthreads();

    // ---- streaming offsets (int, fits: max index < 2^27) ----
    int xoff  = b0;
    int n1off = b0 * N1 + row1;
    int n2off = b0 * N2 + row2;
    int yoff  = b0;

    for (int t = 0; t < T_STEPS; t++) {
        const int cur = t & 1, nxt = cur ^ 1;

        float2 xv = *(const float2*)(inp + xoff);
        float n10 = __ldg(noise1 + n1off), n11 = __ldg(noise1 + n1off + N1);
        float n20 = __ldg(noise2 + n2off), n21 = __ldg(noise2 + n2off + N2);

        // ---- phase A: acc_e = W22[row2,:] . r2_old[e] ----
        const ulonglong2* v2c0 = (const ulonglong2*)s2buf[cur][0];
        const ulonglong2* v2c1 = (const ulonglong2*)s2buf[cur][1];
        ull acc0 = 0, acc1 = 0;
        #pragma unroll
        for (int k = 0; k < 15; k++) {
            ulonglong2 u0 = v2c0[k];
            ulonglong2 u1 = v2c1[k];
            acc0 = ffma2(w22[2 * k],     u0.x, acc0);
            acc0 = ffma2(w22[2 * k + 1], u0.y, acc0);
            acc1 = ffma2(w22[2 * k],     u1.x, acc1);
            acc1 = ffma2(w22[2 * k + 1], u1.y, acc1);
        }

        // ---- phase B: r1 half-dots, combine with shfl_xor(1) ----
        const ulonglong2* v1c0 = (const ulonglong2*)s1buf[cur][0] + half * 4;
        const ulonglong2* v1c1 = (const ulonglong2*)s1buf[cur][1] + half * 4;
        ull a10 = 0, a11 = 0;
        #pragma unroll
        for (int k = 0; k < 4; k++) {
            ulonglong2 u0 = v1c0[k];
            ulonglong2 u1 = v1c1[k];
            a10 = ffma2(w11h[2 * k],     u0.x, a10);
            a10 = ffma2(w11h[2 * k + 1], u0.y, a10);
            a11 = ffma2(w11h[2 * k],     u1.x, a11);
            a11 = ffma2(w11h[2 * k + 1], u1.y, a11);
        }
        float p0 = hadd2(a10);
        float p1 = hadd2(a11);
        p0 += __shfl_xor_sync(0xffffffffu, p0, 1);
        p1 += __shfl_xor_sync(0xffffffffu, p1, 1);
        float r10 = ftanh(p0 + fmaf(winl, xv.x, n10));
        float r11 = ftanh(p1 + fmaf(winl, xv.y, n11));
        if (act2 && half == 0) {
            s1buf[nxt][0][row1] = r10;      // publish r1_new to NEXT buffer
            s1buf[nxt][1][row1] = r11;
        }
        __syncthreads();                     // bar1: r1_new visible

        // ---- phase C: acc_e += W21m[row2,:] . r1_new[e] ----
        const ulonglong2* v1n0 = (const ulonglong2*)s1buf[nxt][0];
        const ulonglong2* v1n1 = (const ulonglong2*)s1buf[nxt][1];
        #pragma unroll
        for (int k = 0; k < 7; k++) {
            ulonglong2 u0 = v1n0[k];
            ulonglong2 u1 = v1n1[k];
            acc0 = ffma2(w21[2 * k],     u0.x, acc0);
            acc0 = ffma2(w21[2 * k + 1], u0.y, acc0);
            acc1 = ffma2(w21[2 * k],     u1.x, acc1);
            acc1 = ffma2(w21[2 * k + 1], u1.y, acc1);
        }
        {
            ull u0 = ((const ull*)s1buf[nxt][0])[14];   // floats 28,29
            ull u1 = ((const ull*)s1buf[nxt][1])[14];
            acc0 = ffma2(w21[14], u0, acc0);
            acc1 = ffma2(w21[14], u1, acc1);
        }

        // ---- phase D: tanh, publish r2, y reduction ----
        float r20 = ftanh(n20 + hadd2(acc0));
        float r21 = ftanh(n21 + hadd2(acc1));
        if (act2) {
            s2buf[nxt][0][row2] = r20;
            s2buf[nxt][1][row2] = r21;
        }
        float y0 = woutl * r20;              // 0 on inactive lanes
        float y1 = woutl * r21;
        #pragma unroll
        for (int o = 16; o > 0; o >>= 1) {
            y0 += __shfl_xor_sync(0xffffffffu, y0, o);
            y1 += __shfl_xor_sync(0xffffffffu, y1, o);
        }
        if (l == 0) ypart[w] = make_float2(y0, y1);

        __syncthreads();                     // bar2: r2_new + ypart visible

        if (tid == 0) {                      // overlaps next step's phase A
            float2 pa = ypart[0], pb = ypart[1];
            *(float2*)(out + yoff) = make_float2(pa.x + pb.x, pa.y + pb.y);
        }

        xoff  += BATCH;
        n1off += BATCH * N1;
        n2off += BATCH * N2;
        yoff  += BATCH;
    }
}

extern "C" void kernel_launch(void* const* d_in, const int* in_sizes, int n_in,
                              void* d_out, int out_size)
{
    const float *inp = nullptr, *n1 = nullptr, *n2 = nullptr;
    const float *W11 = nullptr, *W22 = nullptr, *W21 = nullptr, *M21 = nullptr;
    const float *Win = nullptr, *Wout = nullptr;

    for (int i = 0; i < n_in; i++) {
        const float* p = (const float*)d_in[i];
        switch (in_sizes[i]) {
            case T_STEPS * BATCH:          inp = p; break;
            case T_STEPS * BATCH * N1:     n1  = p; break;
            case T_STEPS * BATCH * N2:     n2  = p; break;
            case N1 * N1:                  W11 = p; break;
            case N2 * N2:                  W22 = p; break;
            case N2 * N1:                                   // appears twice (W21, mask)
                if (!W21) W21 = p; else M21 = p;            // product commutes
                break;
            case N1:                       Win = p; break;
            case N2:                       Wout = p; break;
        }
    }

    // 1024 blocks x 2 warps, 2 batch elems per block; 7 blocks/SM -> single wave
    hier_rnn_kernel<<<BATCH / 2, 64>>>(inp, n1, n2, W11, W22, W21, M21, Win, Wout,
                                       (float*)d_out);
}

// round 9
// speedup vs baseline: 1.1384x; 1.1384x over previous
#include <cuda_runtime.h>

#define T_STEPS 1024
#define BATCH   2048
#define N1      30
#define N2      60

using ull = unsigned long long;

// packed fp32x2 FMA
__device__ __forceinline__ ull ffma2(ull a, ull b, ull c) {
    ull d;
    asm("fma.rn.f32x2 %0, %1, %2, %3;" : "=l"(d) : "l"(a), "l"(b), "l"(c));
    return d;
}
__device__ __forceinline__ ull pk2(float x, float y) {
    ull r;
    asm("mov.b64 %0, {%1, %2};" : "=l"(r) : "f"(x), "f"(y));
    return r;
}
__device__ __forceinline__ float hadd2(ull v) {
    float a, b;
    asm("mov.b64 {%0, %1}, %2;" : "=f"(a), "=f"(b) : "l"(v));
    return a + b;
}
__device__ __forceinline__ float ftanh(float x) {
    float e = __expf(-2.f * x);
    return __fdividef(1.f - e, 1.f + e);
}

#define W11_STRIDE 34   // floats per row: bank=(2r+2j)%32 -> conflict-free for 15 rows/warp

// Block = 64 threads = 2 warps, owning batch pair (b0, b0+1).
// r2: warp w lane l<30 owns row2 = w*30+l -> W22 row (60 regs) + W21m row (30 regs)
// r1: warp w lanes l<15 own row1 = w*15+l -> W11 row read from conflict-free smem table
__global__ void __launch_bounds__(64, 8) hier_rnn_kernel(
    const float* __restrict__ inp,    // (T, B, 1)
    const float* __restrict__ noise1, // (T, B, N1)
    const float* __restrict__ noise2, // (T, B, N2)
    const float* __restrict__ W11,    // (N1, N1)
    const float* __restrict__ W22,    // (N2, N2)
    const float* __restrict__ W21,    // (N2, N1)
    const float* __restrict__ M21,    // (N2, N1)
    const float* __restrict__ Win,    // (N1,)
    const float* __restrict__ Wout,   // (N2,)
    float* __restrict__ out)          // (T, B, 1)
{
    __shared__ __align__(16) float s1buf[2][2][32];   // [buf][elem][slot], pads 30,31 = 0
    __shared__ __align__(16) float s2buf[2][2][64];   // [buf][elem][row], 60 used
    __shared__ __align__(8)  float sW11[N1][W11_STRIDE]; // cols 30..33 zero
    __shared__ float2 ypart[2];

    const int tid = threadIdx.x;
    const int w   = tid >> 5;
    const int l   = tid & 31;
    const int b0  = blockIdx.x * 2;

    const bool act2 = (l < 30);                   // owns an r2 row
    const bool act1 = (l < 15);                   // owns an r1 row
    const int  row2 = w * 30 + (act2 ? l : 29);   // clamped
    const int  row1 = w * 15 + (act1 ? l : 0);    // clamped (inactive alias lane0 = broadcast)

    // ---- weights in registers: 60 + 30 = 90 regs ----
    ull w22[30];
    #pragma unroll
    for (int k = 0; k < 30; k++) {
        float2 v = act2 ? *(const float2*)(W22 + row2 * N2 + 2 * k) : make_float2(0.f, 0.f);
        w22[k] = pk2(v.x, v.y);
    }
    ull w21[15];
    #pragma unroll
    for (int k = 0; k < 15; k++) {
        float2 v = act2 ? *(const float2*)(W21 + row2 * N1 + 2 * k) : make_float2(0.f, 0.f);
        float2 m = act2 ? *(const float2*)(M21 + row2 * N1 + 2 * k) : make_float2(0.f, 0.f);
        w21[k] = pk2(v.x * m.x, v.y * m.y);
    }
    const float winl  = act1 ? Win[row1]  : 0.f;
    const float woutl = act2 ? Wout[row2] : 0.f;

    // ---- W11 smem table (stride-34 rows, conflict-free float2 reads) ----
    for (int idx = tid; idx < N1 * W11_STRIDE; idx += 64) {
        int r = idx / W11_STRIDE, c = idx - r * W11_STRIDE;
        sW11[r][c] = (c < N1) ? W11[r * N1 + c] : 0.f;
    }

    // ---- zero state (both buffers; pads stay zero) ----
    ((float*)s1buf)[tid]       = 0.f;  ((float*)s1buf)[tid + 64]  = 0.f;
    ((float*)s2buf)[tid]       = 0.f;  ((float*)s2buf)[tid + 64]  = 0.f;
    ((float*)s2buf)[tid + 128] = 0.f;  ((float*)s2buf)[tid + 192] = 0.f;
    __syncthreads();

    const float* rW11 = &sW11[row1][0];

    // ---- streaming offsets ----
    int xoff  = b0;
    int n1off = b0 * N1 + row1;
    int n2off = b0 * N2 + row2;
    int yoff  = b0;

    for (int t = 0; t < T_STEPS; t++) {
        const int cur = t & 1, nxt = cur ^ 1;

        float2 xv = *(const float2*)(inp + xoff);
        float n10 = __ldg(noise1 + n1off), n11 = __ldg(noise1 + n1off + N1);
        float n20 = __ldg(noise2 + n2off), n21 = __ldg(noise2 + n2off + N2);

        // ---- phase A: acc = W22[row2,:] . r2_old, split x/y chains (depth 15) ----
        const ulonglong2* v2c0 = (const ulonglong2*)s2buf[cur][0];
        const ulonglong2* v2c1 = (const ulonglong2*)s2buf[cur][1];
        ull a0x = 0, a0y = 0, a1x = 0, a1y = 0;
        #pragma unroll
        for (int k = 0; k < 15; k++) {
            ulonglong2 u0 = v2c0[k];
            ulonglong2 u1 = v2c1[k];
            a0x = ffma2(w22[2 * k],     u0.x, a0x);
            a0y = ffma2(w22[2 * k + 1], u0.y, a0y);
            a1x = ffma2(w22[2 * k],     u1.x, a1x);
            a1y = ffma2(w22[2 * k + 1], u1.y, a1y);
        }

        // ---- phase B: r1 update (15 lanes/warp); W11 from conflict-free smem ----
        const ulonglong2* v1c0 = (const ulonglong2*)s1buf[cur][0];
        const ulonglong2* v1c1 = (const ulonglong2*)s1buf[cur][1];
        ull b0a = 0, b1a = 0;
        #pragma unroll
        for (int k = 0; k < 8; k++) {
            float2 wa = *(const float2*)(rW11 + 4 * k);       // cols 4k,4k+1
            float2 wb = *(const float2*)(rW11 + 4 * k + 2);   // cols 4k+2,4k+3 (30+ are 0)
            ull wA = pk2(wa.x, wa.y), wB = pk2(wb.x, wb.y);
            ulonglong2 u0 = v1c0[k];
            ulonglong2 u1 = v1c1[k];
            b0a = ffma2(wA, u0.x, b0a);
            b0a = ffma2(wB, u0.y, b0a);
            b1a = ffma2(wA, u1.x, b1a);
            b1a = ffma2(wB, u1.y, b1a);
        }
        float r10 = ftanh(fmaf(winl, xv.x, n10) + hadd2(b0a));
        float r11 = ftanh(fmaf(winl, xv.y, n11) + hadd2(b1a));
        if (act1) {
            s1buf[nxt][0][row1] = r10;
            s1buf[nxt][1][row1] = r11;
        }
        __syncthreads();                   // bar1: r1_new visible

        // ---- phase C: acc += W21m[row2,:] . r1_new ----
        const ulonglong2* v1n0 = (const ulonglong2*)s1buf[nxt][0];
        const ulonglong2* v1n1 = (const ulonglong2*)s1buf[nxt][1];
        #pragma unroll
        for (int k = 0; k < 7; k++) {
            ulonglong2 u0 = v1n0[k];
            ulonglong2 u1 = v1n1[k];
            a0x = ffma2(w21[2 * k],     u0.x, a0x);
            a0y = ffma2(w21[2 * k + 1], u0.y, a0y);
            a1x = ffma2(w21[2 * k],     u1.x, a1x);
            a1y = ffma2(w21[2 * k + 1], u1.y, a1y);
        }
        {
            ull u0 = ((const ull*)s1buf[nxt][0])[14];   // floats 28,29
            ull u1 = ((const ull*)s1buf[nxt][1])[14];
            a0x = ffma2(w21[14], u0, a0x);
            a1x = ffma2(w21[14], u1, a1x);
        }

        // ---- phase D: tanh, publish r2, y reduction (off recurrence path) ----
        float r20 = ftanh(n20 + (hadd2(a0x) + hadd2(a0y)));
        float r21 = ftanh(n21 + (hadd2(a1x) + hadd2(a1y)));
        if (act2) {
            s2buf[nxt][0][row2] = r20;
            s2buf[nxt][1][row2] = r21;
        }
        float y0 = woutl * r20;            // 0 on inactive lanes
        float y1 = woutl * r21;
        #pragma unroll
        for (int o = 16; o > 0; o >>= 1) {
            y0 += __shfl_xor_sync(0xffffffffu, y0, o);
            y1 += __shfl_xor_sync(0xffffffffu, y1, o);
        }
        if (l == 0) ypart[w] = make_float2(y0, y1);

        __syncthreads();                   // bar2: r2_new + ypart visible

        if (tid == 0) {
            float2 pa = ypart[0], pb = ypart[1];
            *(float2*)(out + yoff) = make_float2(pa.x + pb.x, pa.y + pb.y);
        }

        xoff  += BATCH;
        n1off += BATCH * N1;
        n2off += BATCH * N2;
        yoff  += BATCH;
    }
}

extern "C" void kernel_launch(void* const* d_in, const int* in_sizes, int n_in,
                              void* d_out, int out_size)
{
    const float *inp = nullptr, *n1 = nullptr, *n2 = nullptr;
    const float *W11 = nullptr, *W22 = nullptr, *W21 = nullptr, *M21 = nullptr;
    const float *Win = nullptr, *Wout = nullptr;

    for (int i = 0; i < n_in; i++) {
        const float* p = (const float*)d_in[i];
        switch (in_sizes[i]) {
            case T_STEPS * BATCH:          inp = p; break;
            case T_STEPS * BATCH * N1:     n1  = p; break;
            case T_STEPS * BATCH * N2:     n2  = p; break;
            case N1 * N1:                  W11 = p; break;
            case N2 * N2:                  W22 = p; break;
            case N2 * N1:                                   // appears twice (W21, mask)
                if (!W21) W21 = p; else M21 = p;            // product commutes
                break;
            case N1:                       Win = p; break;
            case N2:                       Wout = p; break;
        }
    }

    // 1024 blocks x 2 warps, 2 batch elems per block; single resident wave
    hier_rnn_kernel<<<BATCH / 2, 64>>>(inp, n1, n2, W11, W22, W21, M21, Win, Wout,
                                       (float*)d_out);
}

// round 10
// speedup vs baseline: 1.8000x; 1.5811x over previous
#include <cuda_runtime.h>

#define T_STEPS 1024
#define BATCH   2048
#define N1      30
#define N2      60

using ull = unsigned long long;

// ---- scratch: per-lane y partials; reduced by a second kernel ----
// [t][batch_pair][lane] = float2(yp_elem0, yp_elem1)   (256 MiB, device bss)
__device__ float2 g_ysc[T_STEPS][BATCH / 2][32];

// packed fp32x2 FMA (Blackwell)
__device__ __forceinline__ ull ffma2(ull a, ull b, ull c) {
    ull d;
    asm("fma.rn.f32x2 %0, %1, %2, %3;" : "=l"(d) : "l"(a), "l"(b), "l"(c));
    return d;
}
__device__ __forceinline__ ull pk2(float x, float y) {
    ull r;
    asm("mov.b64 %0, {%1, %2};" : "=l"(r) : "f"(x), "f"(y));
    return r;
}
__device__ __forceinline__ float hadd2(ull v) {
    float a, b;
    asm("mov.b64 {%0, %1}, %2;" : "=f"(a), "=f"(b) : "l"(v));
    return a + b;
}
// fast tanh, ~1e-6 rel err; pre-activations bounded, no clamp needed
__device__ __forceinline__ float ftanh(float x) {
    float e = __expf(-2.f * x);
    return __fdividef(1.f - e, 1.f + e);
}

#define W11S 34   // smem row stride for W11 (float2 reads, worst 2-way conflict)

__global__ void __launch_bounds__(128) hier_rnn_kernel(
    const float* __restrict__ inp,    // (T, B, 1)
    const float* __restrict__ noise1, // (T, B, N1)
    const float* __restrict__ noise2, // (T, B, N2)
    const float* __restrict__ W11,    // (N1, N1)
    const float* __restrict__ W22,    // (N2, N2)
    const float* __restrict__ W21,    // (N2, N1)
    const float* __restrict__ M21,    // (N2, N1)
    const float* __restrict__ Win,    // (N1,)
    const float* __restrict__ Wout)   // (N2,)
{
    // per-warp, per-batch-element state buffers (R2 layout)
    __shared__ __align__(16) float s1buf[4][2][32];
    __shared__ __align__(16) float s2buf[4][2][64];
    __shared__ __align__(8)  float sW11[N1][W11S];   // cols 30..33 zero

    const int tid  = threadIdx.x;
    const int warp = tid >> 5;
    const int l    = tid & 31;
    const int gw   = blockIdx.x * 4 + warp;     // batch-pair index
    const int b0   = gw * 2;                    // this warp owns batch b0, b0+1

    float* s1_0 = s1buf[warp][0];
    float* s1_1 = s1buf[warp][1];
    float* s2_0 = s2buf[warp][0];
    float* s2_1 = s2buf[warp][1];

    const bool act = (l < N1);
    const int  ls  = act ? l : 0;
    const int  ra  = 2 * ls;
    const int  rb  = 2 * ls + 1;

    // ---- W21m + W22 in registers (180 regs); W11 goes to smem ----
    ull w21ap[15], w21bp[15], w22ap[30], w22bp[30];
    #pragma unroll
    for (int k = 0; k < 15; k++) {
        float2 w = act ? *(const float2*)(W21 + ra * N1 + 2 * k) : make_float2(0.f, 0.f);
        float2 m = act ? *(const float2*)(M21 + ra * N1 + 2 * k) : make_float2(0.f, 0.f);
        w21ap[k] = pk2(w.x * m.x, w.y * m.y);
        w = act ? *(const float2*)(W21 + rb * N1 + 2 * k) : make_float2(0.f, 0.f);
        m = act ? *(const float2*)(M21 + rb * N1 + 2 * k) : make_float2(0.f, 0.f);
        w21bp[k] = pk2(w.x * m.x, w.y * m.y);
    }
    #pragma unroll
    for (int k = 0; k < 30; k++) {
        float2 w = act ? *(const float2*)(W22 + ra * N2 + 2 * k) : make_float2(0.f, 0.f);
        w22ap[k] = pk2(w.x, w.y);
        w = act ? *(const float2*)(W22 + rb * N2 + 2 * k) : make_float2(0.f, 0.f);
        w22bp[k] = pk2(w.x, w.y);
    }
    const float winl  = act ? Win[l]   : 0.f;
    const float wouta = act ? Wout[ra] : 0.f;
    const float woutb = act ? Wout[rb] : 0.f;

    // ---- W11 smem table (block-shared) ----
    for (int idx = tid; idx < N1 * W11S; idx += 128) {
        int r = idx / W11S, c = idx - r * W11S;
        sW11[r][c] = (c < N1) ? W11[r * N1 + c] : 0.f;
    }

    // ---- zero state ----
    s1_0[l] = 0.f; s1_1[l] = 0.f;
    s2_0[l] = 0.f; s2_0[l + 32] = 0.f;
    s2_1[l] = 0.f; s2_1[l + 32] = 0.f;
    __syncthreads();

    const float* rw = &sW11[ls][0];   // this lane's W11 row (inactive -> row 0, harmless)

    // ---- streaming pointers ----
    const float* pn1 = noise1 + (long long)b0 * N1 + ls;
    const float* pn2 = noise2 + (long long)b0 * N2 + ra;
    const float* px  = inp + b0;

    float2 xv   = *(const float2*)px;
    float  n1v0 = __ldg(pn1);
    float  n1v1 = __ldg(pn1 + N1);
    float2 n2v0 = *(const float2*)pn2;
    float2 n2v1 = *(const float2*)(pn2 + N2);

    const ulonglong2* v1_0 = (const ulonglong2*)s1_0;
    const ulonglong2* v1_1 = (const ulonglong2*)s1_1;
    const ulonglong2* v2_0 = (const ulonglong2*)s2_0;
    const ulonglong2* v2_1 = (const ulonglong2*)s2_1;
    const ull* s1w_0 = (const ull*)s1_0;
    const ull* s1w_1 = (const ull*)s1_1;

    for (int t = 0; t < T_STEPS; t++) {
        // one-step-ahead prefetch (covers DRAM latency)
        float2 xn  = make_float2(0.f, 0.f);
        float  n1n0 = 0.f, n1n1 = 0.f;
        float2 n2n0 = make_float2(0.f, 0.f), n2n1 = make_float2(0.f, 0.f);
        if (t + 1 < T_STEPS) {
            px  += BATCH;
            pn1 += BATCH * N1;
            pn2 += BATCH * N2;
            xn   = *(const float2*)px;
            n1n0 = __ldg(pn1);
            n1n1 = __ldg(pn1 + N1);
            n2n0 = *(const float2*)pn2;
            n2n1 = *(const float2*)(pn2 + N2);
        }

        // ---- W22 part: 4 independent chains ----
        ull a2a0 = 0, a2b0 = 0, a2a1 = 0, a2b1 = 0;
        #pragma unroll
        for (int k = 0; k < 15; k++) {
            ulonglong2 u0 = v2_0[k];
            ulonglong2 u1 = v2_1[k];
            a2a0 = ffma2(w22ap[2 * k],     u0.x, a2a0);
            a2a0 = ffma2(w22ap[2 * k + 1], u0.y, a2a0);
            a2b0 = ffma2(w22bp[2 * k],     u0.x, a2b0);
            a2b0 = ffma2(w22bp[2 * k + 1], u0.y, a2b0);
            a2a1 = ffma2(w22ap[2 * k],     u1.x, a2a1);
            a2a1 = ffma2(w22ap[2 * k + 1], u1.y, a2a1);
            a2b1 = ffma2(w22bp[2 * k],     u1.x, a2b1);
            a2b1 = ffma2(w22bp[2 * k + 1], u1.y, a2b1);
        }

        // ---- r1 update: W11 from smem (weights shared across both elems) ----
        ull a1_0 = 0, a1_1 = 0;
        #pragma unroll
        for (int k = 0; k < 7; k++) {
            float2 wx = *(const float2*)(rw + 4 * k);       // cols 4k,4k+1
            float2 wy = *(const float2*)(rw + 4 * k + 2);   // cols 4k+2,4k+3
            ull wX = pk2(wx.x, wx.y), wY = pk2(wy.x, wy.y);
            ulonglong2 u0 = v1_0[k];
            ulonglong2 u1 = v1_1[k];
            a1_0 = ffma2(wX, u0.x, a1_0);
            a1_0 = ffma2(wY, u0.y, a1_0);
            a1_1 = ffma2(wX, u1.x, a1_1);
            a1_1 = ffma2(wY, u1.y, a1_1);
        }
        {
            float2 wt = *(const float2*)(rw + 28);          // cols 28,29
            ull wT = pk2(wt.x, wt.y);
            a1_0 = ffma2(wT, s1w_0[14], a1_0);
            a1_1 = ffma2(wT, s1w_1[14], a1_1);
        }

        float r1n0 = ftanh(fmaf(winl, xv.x, n1v0) + hadd2(a1_0));
        float r1n1 = ftanh(fmaf(winl, xv.y, n1v1) + hadd2(a1_1));

        __syncwarp();                    // all old-r1 reads done
        if (act) { s1_0[l] = r1n0; s1_1[l] = r1n1; }
        __syncwarp();

        // ---- W21m part on fresh r1 ----
        #pragma unroll
        for (int k = 0; k < 7; k++) {
            ulonglong2 u0 = v1_0[k];
            ulonglong2 u1 = v1_1[k];
            a2a0 = ffma2(w21ap[2 * k],     u0.x, a2a0);
            a2b0 = ffma2(w21bp[2 * k],     u0.x, a2b0);
            a2a1 = ffma2(w21ap[2 * k],     u1.x, a2a1);
            a2b1 = ffma2(w21bp[2 * k],     u1.x, a2b1);
            a2a0 = ffma2(w21ap[2 * k + 1], u0.y, a2a0);
            a2b0 = ffma2(w21bp[2 * k + 1], u0.y, a2b0);
            a2a1 = ffma2(w21ap[2 * k + 1], u1.y, a2a1);
            a2b1 = ffma2(w21bp[2 * k + 1], u1.y, a2b1);
        }
        {
            ull u0 = s1w_0[14];
            ull u1 = s1w_1[14];
            a2a0 = ffma2(w21ap[14], u0, a2a0);
            a2b0 = ffma2(w21bp[14], u0, a2b0);
            a2a1 = ffma2(w21ap[14], u1, a2a1);
            a2b1 = ffma2(w21bp[14], u1, a2b1);
        }

        float r2a0 = ftanh(n2v0.x + hadd2(a2a0));
        float r2b0 = ftanh(n2v0.y + hadd2(a2b0));
        float r2a1 = ftanh(n2v1.x + hadd2(a2a1));
        float r2b1 = ftanh(n2v1.y + hadd2(a2b1));

        __syncwarp();                    // order the publish after old-r2 reads
        if (act) {
            *(float2*)(s2_0 + ra) = make_float2(r2a0, r2b0);
            *(float2*)(s2_1 + ra) = make_float2(r2a1, r2b1);
        }

        // ---- y partials: NO in-warp reduction; fire-and-forget streaming store ----
        float yp0 = wouta * r2a0 + woutb * r2b0;   // 0 on inactive lanes
        float yp1 = wouta * r2a1 + woutb * r2b1;
        __stcs(&g_ysc[t][gw][l], make_float2(yp0, yp1));

        __syncwarp();                    // publishes visible before next step's reads

        xv = xn; n1v0 = n1n0; n1v1 = n1n1; n2v0 = n2n0; n2v1 = n2n1;
    }
}

// reduce 32 lane-partials -> y[t][b] for the whole (T, B) grid; memory-bound, ~60us
__global__ void __launch_bounds__(256) reduce_y(float* __restrict__ out)
{
    const int gw = blockIdx.x * 8 + (threadIdx.x >> 5);   // 0 .. T*B/2-1
    const int l  = threadIdx.x & 31;
    const int t  = gw >> 10;          // / (BATCH/2)
    const int wp = gw & 1023;

    float2 v = __ldcs(&g_ysc[t][wp][l]);
    #pragma unroll
    for (int o = 16; o > 0; o >>= 1) {
        v.x += __shfl_xor_sync(0xffffffffu, v.x, o);
        v.y += __shfl_xor_sync(0xffffffffu, v.y, o);
    }
    if (l == 0) *(float2*)(out + t * BATCH + 2 * wp) = v;
}

extern "C" void kernel_launch(void* const* d_in, const int* in_sizes, int n_in,
                              void* d_out, int out_size)
{
    const float *inp = nullptr, *n1 = nullptr, *n2 = nullptr;
    const float *W11 = nullptr, *W22 = nullptr, *W21 = nullptr, *M21 = nullptr;
    const float *Win = nullptr, *Wout = nullptr;

    for (int i = 0; i < n_in; i++) {
        const float* p = (const float*)d_in[i];
        switch (in_sizes[i]) {
            case T_STEPS * BATCH:          inp = p; break;
            case T_STEPS * BATCH * N1:     n1  = p; break;
            case T_STEPS * BATCH * N2:     n2  = p; break;
            case N1 * N1:                  W11 = p; break;
            case N2 * N2:                  W22 = p; break;
            case N2 * N1:                                   // appears twice (W21, mask)
                if (!W21) W21 = p; else M21 = p;            // product commutes
                break;
            case N1:                       Win = p; break;
            case N2:                       Wout = p; break;
        }
    }

    // 256 blocks x 4 warps x 2 batch elements = 2048 (R2 config)
    hier_rnn_kernel<<<BATCH / 8, 128>>>(inp, n1, n2, W11, W22, W21, M21, Win, Wout);
    // reduce all (t, b) partials into the output
    reduce_y<<<(T_STEPS * (BATCH / 2)) / 8, 256>>>((float*)d_out);
}